// round 16
// baseline (speedup 1.0000x reference)
#include <cuda_runtime.h>
#include <math.h>

#define SEQ  131072
#define H    50
#define HP   56            // h row width (14 float4)
#define NL   5
#define NC   512           // chunks
#define B    256           // valid steps per chunk
#define WU   64            // warm-up steps (chunk 0: 0). rho~0.8 -> residual ~7e-7. DO NOT REDUCE.
#define SPANMAX (B + WU)   // 320
#define PRW  64            // pre row width (floats)
#define RT   32            // gemm rows per block

#define TANH_K 2.8853900817779268f   // 2*log2(e), folded into weights/bias

// Device-global streams. Pads / unused tail rows are never written -> stay 0.
__device__ __align__(128) float g_pre [NC * SPANMAX * PRW];   // pre-activations (scaled)
__device__ __align__(128) float g_buf0[NC * SPANMAX * HP];
__device__ __align__(128) float g_buf1[NC * SPANMAX * HP];

// ---- packed f32x2 helpers ----
typedef unsigned long long u64;
__device__ __forceinline__ u64 pk2(float lo, float hi) {
    u64 r; asm("mov.b64 %0, {%1, %2};" : "=l"(r) : "f"(lo), "f"(hi)); return r;
}
__device__ __forceinline__ u64 ffma2(u64 a, u64 b, u64 c) {
    u64 d; asm("fma.rn.f32x2 %0, %1, %2, %3;" : "=l"(d) : "l"(a), "l"(b), "l"(c)); return d;
}
__device__ __forceinline__ u64 addx2(u64 a, u64 b) {
    u64 d; asm("add.rn.f32x2 %0, %1, %2;" : "=l"(d) : "l"(a), "l"(b)); return d;
}
__device__ __forceinline__ float2 upk2(u64 v) {
    float lo, hi; asm("mov.b64 {%0, %1}, %2;" : "=f"(lo), "=f"(hi) : "l"(v));
    return make_float2(lo, hi);
}
__device__ __forceinline__ float red4(u64 a0, u64 a1, u64 a2, u64 a3) {
    float2 f = upk2(addx2(addx2(a0, a1), addx2(a2, a3)));
    return f.x + f.y;
}

// tanh with PRE-SCALED input: expects s' = 2*log2(e)*s. tanh = 1 - 2/(2^s' + 1).
__device__ __forceinline__ float tanh_pre(float sp) {
    float e, r;
    asm("ex2.approx.f32 %0, %1;" : "=f"(e) : "f"(sp));
    float d = e + 1.0f;
    asm("rcp.approx.f32 %0, %1;" : "=f"(r) : "f"(d));
    return fmaf(-2.0f, r, 1.0f);
}

// 52-wide packed dot (26 FFMA2), seed in accumulator lane 0.
__device__ __forceinline__ float dot52x2(const u64* __restrict__ wp,
                                         const float* __restrict__ v, float seed) {
    const ulonglong2* v2 = (const ulonglong2*)v;
    u64 a0 = pk2(seed, 0.f), a1 = 0ull, a2 = 0ull, a3 = 0ull;
#pragma unroll
    for (int q = 0; q < 13; q += 2) {
        ulonglong2 u = v2[q];
        a0 = ffma2(wp[2 * q + 0], u.x, a0);
        a1 = ffma2(wp[2 * q + 1], u.y, a1);
    }
#pragma unroll
    for (int q = 1; q < 13; q += 2) {
        ulonglong2 u = v2[q];
        a2 = ffma2(wp[2 * q + 0], u.x, a2);
        a3 = ffma2(wp[2 * q + 1], u.y, a3);
    }
    return red4(a0, a1, a2, a3);
}

// ---------------------------------------------------------------------------
// GEMM kernels: fill g_pre for one layer, fully parallel.
// ---------------------------------------------------------------------------
__global__ void __launch_bounds__(64)
gemm0(const float* __restrict__ x, const float* __restrict__ Wih0,
      const float* __restrict__ bih, const float* __restrict__ bhh) {
    const int c  = blockIdx.y;
    const int r0 = blockIdx.x * RT;
    const int wu = c ? WU : 0;
    const int span = B + wu;
    if (r0 >= span) return;
    const int g0 = c * B - wu;
    const int j  = threadIdx.x;           // 0..63
    const bool pw = (j < H);

    u64 wp[4];
#pragma unroll
    for (int i = 0; i < 4; i++)
        wp[i] = pw ? pk2(TANH_K * Wih0[j * 8 + 2 * i], TANH_K * Wih0[j * 8 + 2 * i + 1]) : 0ull;
    const float bias = pw ? TANH_K * (bih[j] + bhh[j]) : 0.f;

    __shared__ __align__(16) float xS[RT * 8];
    {
        const float4* s4 = (const float4*)(x + (size_t)(g0 + r0) * 8);
        float4* d4 = (float4*)xS;
        d4[j] = s4[j];                    // 64 float4 = 32 rows x 8
    }
    __syncthreads();

    float* __restrict__ dst = g_pre + (size_t)c * SPANMAX * PRW;
#pragma unroll 4
    for (int i = 0; i < RT; i++) {
        const ulonglong2* v2 = (const ulonglong2*)(xS + i * 8);
        ulonglong2 u0 = v2[0], u1 = v2[1];
        u64 a0 = pk2(bias, 0.f), a1 = 0ull;
        a0 = ffma2(wp[0], u0.x, a0);
        a1 = ffma2(wp[1], u0.y, a1);
        a0 = ffma2(wp[2], u1.x, a0);
        a1 = ffma2(wp[3], u1.y, a1);
        float2 f = upk2(addx2(a0, a1));
        dst[(size_t)(r0 + i) * PRW + j] = f.x + f.y;   // pads j>=50 write 0
    }
}

__global__ void __launch_bounds__(64)
gemmh(const float* __restrict__ src,    // h stream [NC][SPANMAX][HP]
      const float* __restrict__ W,      // this layer's input weights [H][H]
      const float* __restrict__ bi, const float* __restrict__ bh) {
    const int c  = blockIdx.y;
    const int r0 = blockIdx.x * RT;
    const int wu = c ? WU : 0;
    const int span = B + wu;
    if (r0 >= span) return;
    const int j  = threadIdx.x;           // 0..63
    const bool pw = (j < H);

    u64 wp[26];
#pragma unroll
    for (int i = 0; i < 26; i++) {
        float w0 = (pw && 2 * i < H)     ? TANH_K * W[j * H + 2 * i]     : 0.f;
        float w1 = (pw && 2 * i + 1 < H) ? TANH_K * W[j * H + 2 * i + 1] : 0.f;
        wp[i] = pk2(w0, w1);
    }
    const float bias = pw ? TANH_K * (bi[j] + bh[j]) : 0.f;

    __shared__ __align__(16) float hS[RT * HP];
    {
        const float4* s4 = (const float4*)(src + (size_t)c * SPANMAX * HP + (size_t)r0 * HP);
        float4* d4 = (float4*)hS;
#pragma unroll
        for (int idx = j; idx < RT * HP / 4; idx += 64) d4[idx] = s4[idx];
    }
    __syncthreads();

    float* __restrict__ dst = g_pre + (size_t)c * SPANMAX * PRW;
#pragma unroll 2
    for (int i = 0; i < RT; i++)
        dst[(size_t)(r0 + i) * PRW + j] = dot52x2(wp, hS + i * HP, bias);
}

// ---------------------------------------------------------------------------
// Scan kernel: one warp per chunk. Lane computes outputs j0=lane, j1=32+lane.
// h broadcast via 2xHP shared ping-pong; only __syncwarp per step.
// last==1: fused MLP head epilogue over this chunk's B timesteps.
// ---------------------------------------------------------------------------
__global__ void __launch_bounds__(32)
scan_layer(const float* __restrict__ Whh_l,   // this layer's Whh [H][H]
           float* __restrict__ dstbase, int last,
           const float* __restrict__ W1, const float* __restrict__ b1,
           const float* __restrict__ W2, const float* __restrict__ b2,
           float* __restrict__ out) {
    const int c    = blockIdx.x;
    const int lane = threadIdx.x;
    const int wu   = c ? WU : 0;
    const int span = B + wu;
    const int j1   = 32 + lane;
    const bool has1 = (j1 < H);           // lanes 0..17

    __shared__ __align__(16) float hbuf[2 * HP];
    __shared__ __align__(16) float W1s[20 * 52 + 44];   // MLP staging (last layer)

    // packed recurrent weights (j0 = lane always < H since lane < 32 < 50)
    u64 w0p[26], w1p[26];
#pragma unroll
    for (int i = 0; i < 26; i++) {
        float a0 = (2 * i < H)     ? TANH_K * Whh_l[lane * H + 2 * i]     : 0.f;
        float a1 = (2 * i + 1 < H) ? TANH_K * Whh_l[lane * H + 2 * i + 1] : 0.f;
        w0p[i] = pk2(a0, a1);
        float c0 = (has1 && 2 * i < H)     ? TANH_K * Whh_l[j1 * H + 2 * i]     : 0.f;
        float c1 = (has1 && 2 * i + 1 < H) ? TANH_K * Whh_l[j1 * H + 2 * i + 1] : 0.f;
        w1p[i] = pk2(c0, c1);
    }

    const float* __restrict__ pre = g_pre + (size_t)c * SPANMAX * PRW;
    float* __restrict__ dst = dstbase + (size_t)c * SPANMAX * HP;

#pragma unroll
    for (int i = lane; i < 2 * HP; i += 32) hbuf[i] = 0.f;   // h(-1)=0, pads 0
    __syncwarp();

    // depth-2 pre prefetch (j1>=50 lanes read pre pads = 0)
    float pa0 = pre[lane],        pa1 = pre[j1];
    float pb0 = pre[PRW + lane],  pb1 = pre[PRW + j1];

#pragma unroll 2
    for (int t = 0; t < span; t++) {
        const int p = t & 1;
        // dual 52-wide dot sharing the 13 broadcast LDS
        const ulonglong2* v2 = (const ulonglong2*)&hbuf[p * HP];
        u64 a0 = pk2(pa0, 0.f), a1 = 0ull, a2 = 0ull, a3 = 0ull;
        u64 b0 = pk2(pa1, 0.f), b1r = 0ull, b2r = 0ull, b3r = 0ull;
#pragma unroll
        for (int q = 0; q < 13; q += 2) {
            ulonglong2 u = v2[q];
            a0  = ffma2(w0p[2 * q + 0], u.x, a0);
            a1  = ffma2(w0p[2 * q + 1], u.y, a1);
            b0  = ffma2(w1p[2 * q + 0], u.x, b0);
            b1r = ffma2(w1p[2 * q + 1], u.y, b1r);
        }
#pragma unroll
        for (int q = 1; q < 13; q += 2) {
            ulonglong2 u = v2[q];
            a2  = ffma2(w0p[2 * q + 0], u.x, a2);
            a3  = ffma2(w0p[2 * q + 1], u.y, a3);
            b2r = ffma2(w1p[2 * q + 0], u.x, b2r);
            b3r = ffma2(w1p[2 * q + 1], u.y, b3r);
        }
        float s0 = red4(a0, a1, a2, a3);
        float s1 = red4(b0, b1r, b2r, b3r);
        float hv0 = tanh_pre(s0);
        float hv1 = tanh_pre(s1);

        hbuf[(p ^ 1) * HP + lane] = hv0;
        if (has1) hbuf[(p ^ 1) * HP + j1] = hv1;
        dst[(size_t)t * HP + lane] = hv0;
        if (has1) dst[(size_t)t * HP + j1] = hv1;

        const int rn = (t + 2 < span) ? t + 2 : span - 1;
        float pc0 = pre[(size_t)rn * PRW + lane];
        float pc1 = pre[(size_t)rn * PRW + j1];
        pa0 = pb0; pa1 = pb1; pb0 = pc0; pb1 = pc1;
        __syncwarp();          // STS of step t drained before LDS of step t+1
    }

    if (!last) return;

    // ===================== fused MLP head (one warp, B timesteps) ==============
    __threadfence_block();
    __syncwarp();
    float* b1s = W1s + 20 * 52;
    float* W2s = b1s + 20;
#pragma unroll
    for (int i = lane; i < 20 * 52; i += 32) {
        int jq = i / 52, kq = i % 52;
        W1s[i] = (kq < H) ? W1[jq * H + kq] : 0.f;
    }
    if (lane < 20) { b1s[lane] = b1[lane]; W2s[lane] = W2[lane]; }
    __syncwarp();
    const float bb2 = b2[0];

#pragma unroll
    for (int q = lane; q < B; q += 32) {
        const float4* h4 = (const float4*)(dst + (size_t)(wu + q) * HP);
        float acc[20];
#pragma unroll
        for (int jq = 0; jq < 20; jq++) acc[jq] = b1s[jq];
#pragma unroll 4
        for (int kq = 0; kq < 13; kq++) {             // 52 cols; pads 0
            float4 hv = h4[kq];
#pragma unroll
            for (int jq = 0; jq < 20; jq++) {
                acc[jq] = fmaf(W1s[jq * 52 + 4 * kq + 0], hv.x, acc[jq]);
                acc[jq] = fmaf(W1s[jq * 52 + 4 * kq + 1], hv.y, acc[jq]);
                acc[jq] = fmaf(W1s[jq * 52 + 4 * kq + 2], hv.z, acc[jq]);
                acc[jq] = fmaf(W1s[jq * 52 + 4 * kq + 3], hv.w, acc[jq]);
            }
        }
        float v = 0.f;
#pragma unroll
        for (int jq = 0; jq < 20; jq++) v = fmaf(W2s[jq], fmaxf(acc[jq], 0.f), v);
        out[c * B + q] = 1.f / (1.f + expf(-(v + bb2)));
    }
}

// ---------------------------------------------------------------------------
extern "C" void kernel_launch(void* const* d_in, const int* in_sizes, int n_in,
                              void* d_out, int out_size) {
    const float* x    = (const float*)d_in[0];
    const float* Wih0 = (const float*)d_in[1];
    const float* Wr   = (const float*)d_in[2];
    const float* Whh  = (const float*)d_in[3];
    const float* bih  = (const float*)d_in[4];
    const float* bhh  = (const float*)d_in[5];
    const float* W1   = (const float*)d_in[6];
    const float* b1   = (const float*)d_in[7];
    const float* W2   = (const float*)d_in[8];
    const float* b2   = (const float*)d_in[9];
    float* out = (float*)d_out;

    float *buf0, *buf1;
    cudaGetSymbolAddress((void**)&buf0, g_buf0);
    cudaGetSymbolAddress((void**)&buf1, g_buf1);

    const dim3 ggrid(SPANMAX / RT, NC);

    // layer 0
    gemm0<<<ggrid, 64>>>(x, Wih0, bih, bhh);
    scan_layer<<<NC, 32>>>(Whh + 0 * H * H, buf0, 0, W1, b1, W2, b2, out);
    // layer 1
    gemmh<<<ggrid, 64>>>(buf0, Wr + 0 * H * H, bih + 1 * H, bhh + 1 * H);
    scan_layer<<<NC, 32>>>(Whh + 1 * H * H, buf1, 0, W1, b1, W2, b2, out);
    // layer 2
    gemmh<<<ggrid, 64>>>(buf1, Wr + 1 * H * H, bih + 2 * H, bhh + 2 * H);
    scan_layer<<<NC, 32>>>(Whh + 2 * H * H, buf0, 0, W1, b1, W2, b2, out);
    // layer 3
    gemmh<<<ggrid, 64>>>(buf0, Wr + 2 * H * H, bih + 3 * H, bhh + 3 * H);
    scan_layer<<<NC, 32>>>(Whh + 3 * H * H, buf1, 0, W1, b1, W2, b2, out);
    // layer 4 (+ fused MLP head)
    gemmh<<<ggrid, 64>>>(buf1, Wr + 3 * H * H, bih + 4 * H, bhh + 4 * H);
    scan_layer<<<NC, 32>>>(Whh + 4 * H * H, buf0, 1, W1, b1, W2, b2, out);
}

// round 17
// speedup vs baseline: 1.5102x; 1.5102x over previous
#include <cuda_runtime.h>
#include <math.h>

#define SEQ  131072
#define H    50
#define HP   56            // padded row width (14 float4)
#define NL   5
#define NC   512           // chunks; 2 per block -> 256 blocks
#define B    256           // valid steps per chunk
#define WU   64            // warm-up steps (chunk 0: 0). rho~0.8 -> residual ~7e-7. DO NOT REDUCE.
#define SPANMAX (B + WU)   // 320
#define TILE 32            // steps per tile
#define PRW  56            // pre row width

#define TANH_K 2.8853900817779268f   // 2*log2(e), folded into weights/bias

// Per-chunk ping-pong h streams (pads [50,56) never written -> stay 0).
__device__ __align__(128) float g_buf0[NC * SPANMAX * HP];
__device__ __align__(128) float g_buf1[NC * SPANMAX * HP];

// named barriers: 1+ch compute(64), 3+ch producer(64), 5+ch chunk-wide(128)
__device__ __forceinline__ void barC(int ch)  { asm volatile("bar.sync %0, 64;"  :: "r"(1 + ch) : "memory"); }
__device__ __forceinline__ void barP(int ch)  { asm volatile("bar.sync %0, 64;"  :: "r"(3 + ch) : "memory"); }
__device__ __forceinline__ void barA(int ch)  { asm volatile("bar.sync %0, 128;" :: "r"(5 + ch) : "memory"); }

// ---- packed f32x2 helpers (producer GEMM only) ----
typedef unsigned long long u64;
__device__ __forceinline__ u64 pk2(float lo, float hi) {
    u64 r; asm("mov.b64 %0, {%1, %2};" : "=l"(r) : "f"(lo), "f"(hi)); return r;
}
__device__ __forceinline__ u64 ffma2(u64 a, u64 b, u64 c) {
    u64 d; asm("fma.rn.f32x2 %0, %1, %2, %3;" : "=l"(d) : "l"(a), "l"(b), "l"(c)); return d;
}
__device__ __forceinline__ u64 addx2(u64 a, u64 b) {
    u64 d; asm("add.rn.f32x2 %0, %1, %2;" : "=l"(d) : "l"(a), "l"(b)); return d;
}
__device__ __forceinline__ float2 upk2(u64 v) {
    float lo, hi; asm("mov.b64 {%0, %1}, %2;" : "=f"(lo), "=f"(hi) : "l"(v));
    return make_float2(lo, hi);
}

// tanh with PRE-SCALED input: expects s' = 2*log2(e)*s. tanh = 1 - 2/(2^s' + 1).
__device__ __forceinline__ float tanh_pre(float sp) {
    float e, r;
    asm("ex2.approx.f32 %0, %1;" : "=f"(e) : "f"(sp));
    float d = e + 1.0f;
    asm("rcp.approx.f32 %0, %1;" : "=f"(r) : "f"(d));
    return fmaf(-2.0f, r, 1.0f);
}

// scalar 52-wide dot (compute side; proven config)
__device__ __forceinline__ float dot52(const float* __restrict__ w,
                                       const float4* __restrict__ v, float seed) {
    float a0 = seed, a1 = 0.f, a2 = 0.f, a3 = 0.f;
#pragma unroll
    for (int q = 0; q < 13; q++) {
        float4 vv = v[q];
        a0 = fmaf(w[4 * q + 0], vv.x, a0);
        a1 = fmaf(w[4 * q + 1], vv.y, a1);
        a2 = fmaf(w[4 * q + 2], vv.z, a2);
        a3 = fmaf(w[4 * q + 3], vv.w, a3);
    }
    return (a0 + a1) + (a2 + a3);
}

// packed 52-wide dot (producer side; pure throughput)
__device__ __forceinline__ float dot52x2(const u64* __restrict__ wp,
                                         const float* __restrict__ v, float seed) {
    const ulonglong2* v2 = (const ulonglong2*)v;   // 13 x 16B
    u64 a0 = pk2(seed, 0.f), a1 = 0ull, a2 = 0ull, a3 = 0ull;
#pragma unroll
    for (int q = 0; q < 13; q += 2) {
        ulonglong2 u = v2[q];
        a0 = ffma2(wp[2 * q + 0], u.x, a0);
        a1 = ffma2(wp[2 * q + 1], u.y, a1);
    }
#pragma unroll
    for (int q = 1; q < 13; q += 2) {
        ulonglong2 u = v2[q];
        a2 = ffma2(wp[2 * q + 0], u.x, a2);
        a3 = ffma2(wp[2 * q + 1], u.y, a3);
    }
    float2 f = upk2(addx2(addx2(a0, a1), addx2(a2, a3)));
    return f.x + f.y;
}

// ---------------------------------------------------------------------------
// 2 chunks per 256-thread block. Per chunk (128 threads):
//   local tids 0..63  : compute — 1 thread per output, scalar register weights
//   local tids 64..127: producers — 1 thread per output, PACKED register weights
// ---------------------------------------------------------------------------
__global__ void __launch_bounds__(256, 2)
rnn_chunks(const float* __restrict__ x,    const float* __restrict__ Wih0,
           const float* __restrict__ Wr,   const float* __restrict__ Whh,
           const float* __restrict__ bih,  const float* __restrict__ bhh,
           const float* __restrict__ W1,   const float* __restrict__ b1,
           const float* __restrict__ W2,   const float* __restrict__ b2,
           float* __restrict__ out) {
    const int tid = threadIdx.x;
    const int ch  = tid >> 7;                 // chunk half within block
    const int lt  = tid & 127;                // id within chunk
    const int c   = blockIdx.x * 2 + ch;      // global chunk id
    const int wu  = c ? WU : 0;
    const int T   = (B + wu) / TILE;          // 8 or 10 tiles
    const int g0  = c * B - wu;               // global step of local step 0

    __shared__ __align__(16) float preS[2][2][TILE * PRW]; // [ch][slot] ~28.7 KB
    __shared__ __align__(16) float inS[2][TILE * HP];      // ~14.3 KB (reused in epilogue)
    __shared__ __align__(16) float hbuf[2][2 * HP];

    float* __restrict__ buf0 = g_buf0 + (size_t)c * SPANMAX * HP;
    float* __restrict__ buf1 = g_buf1 + (size_t)c * SPANMAX * HP;

    if (lt < 64) {
        // ============================ compute (2 warps) ============================
        const int j  = lt;                    // output index (j>=50 inert)
        const int jr = (j < H) ? j : 0;       // clamped pre-read index
        const bool wr = (j < H);

        for (int l = 0; l < NL; l++) {
            float whh[52];
#pragma unroll
            for (int i = 0; i < 52; i++)
                whh[i] = (j < H && i < H) ? TANH_K * Whh[(l * H + j) * H + i] : 0.f;
            float* __restrict__ dst = (l & 1) ? buf1 : buf0;

            for (int i = lt; i < 2 * HP; i += 64) hbuf[ch][i] = 0.f;   // h(-1)=0

            for (int k = 0; k < T; k++) {
                barA(ch);                                 // slot k&1 staged
                const float* __restrict__ pre = preS[ch][k & 1];
                float pcur = pre[jr];
                const int tbase = k * TILE;
#pragma unroll 4
                for (int i = 0; i < TILE; i++) {
                    const int p = i & 1;
                    barC(ch);                             // h(t-1) visible
                    float s = dot52(whh, (const float4*)&hbuf[ch][p * HP], pcur);
                    float hv = tanh_pre(s);
                    if (wr) hbuf[ch][(p ^ 1) * HP + j] = hv;
                    if (wr) dst[(size_t)(tbase + i) * HP + j] = hv;
                    pcur = pre[((i + 1) & (TILE - 1)) * PRW + jr];
                }
            }
            barA(ch);                                     // layer end: dst complete
        }
    } else {
        // ============================ producers (2 warps) ==========================
        const int jj = lt - 64;                           // output 0..63 (>=50 inert)
        const bool pw = (jj < H);

        for (int l = 0; l < NL; l++) {
            u64 wp[26];
            float bias = 0.f;
            if (l == 0) {
#pragma unroll
                for (int i = 0; i < 26; i++) {
                    float w0 = (pw && 2 * i < 8)     ? TANH_K * Wih0[jj * 8 + 2 * i]     : 0.f;
                    float w1 = (pw && 2 * i + 1 < 8) ? TANH_K * Wih0[jj * 8 + 2 * i + 1] : 0.f;
                    wp[i] = pk2(w0, w1);
                }
            } else {
#pragma unroll
                for (int i = 0; i < 26; i++) {
                    float w0 = (pw && 2 * i < H)     ? TANH_K * Wr[((l - 1) * H + jj) * H + 2 * i]     : 0.f;
                    float w1 = (pw && 2 * i + 1 < H) ? TANH_K * Wr[((l - 1) * H + jj) * H + 2 * i + 1] : 0.f;
                    wp[i] = pk2(w0, w1);
                }
            }
            if (pw) bias = TANH_K * (bih[l * H + jj] + bhh[l * H + jj]);

            const float* __restrict__ src = (l == 0) ? x : ((l & 1) ? buf0 : buf1);

            auto produce = [&](int k) {
                const int base = k * TILE;
                if (l == 0) {   // stage TILE rows of x (8 floats each)
                    const float4* s4 = (const float4*)(x + (size_t)(g0 + base) * 8);
                    float4* d4 = (float4*)inS[ch];
                    for (int idx = jj; idx < TILE * 2; idx += 64) d4[idx] = s4[idx];
                } else {        // stage TILE rows of h (HP floats each)
                    const float4* s4 = (const float4*)(src + (size_t)base * HP);
                    float4* d4 = (float4*)inS[ch];
                    for (int idx = jj; idx < TILE * HP / 4; idx += 64) d4[idx] = s4[idx];
                }
                barP(ch);
                float* __restrict__ slot = preS[ch][k & 1];
                if (l == 0) {
                    for (int i = 0; i < TILE; i++) {
                        const ulonglong2* v2 = (const ulonglong2*)(inS[ch] + i * 8);
                        ulonglong2 u0 = v2[0], u1 = v2[1];
                        u64 a0 = pk2(bias, 0.f), a1 = 0ull;
                        a0 = ffma2(wp[0], u0.x, a0);
                        a1 = ffma2(wp[1], u0.y, a1);
                        a0 = ffma2(wp[2], u1.x, a0);
                        a1 = ffma2(wp[3], u1.y, a1);
                        float2 f = upk2(addx2(a0, a1));
                        if (pw) slot[i * PRW + jj] = f.x + f.y;
                    }
                } else {
                    for (int i = 0; i < TILE; i++) {
                        float acc = dot52x2(wp, inS[ch] + i * HP, bias);
                        if (pw) slot[i * PRW + jj] = acc;
                    }
                }
                barP(ch);     // all dots read inS before next staging overwrites it
            };

            produce(0);
            for (int k = 0; k < T; k++) {
                barA(ch);                     // compute takes slot k; other slot free
                if (k + 1 < T) produce(k + 1);
            }
            barA(ch);                         // layer end
        }
    }

    // ===================== fused MLP head (all 256 threads) =====================
    __syncthreads();          // both chunks finished; buf0 STGs ordered
    {
        float* W1s = inS[0];            // 20 x 52, zero-padded
        float* b1s = inS[0] + 1040;     // 20
        float* W2s = inS[0] + 1060;     // 20
        for (int i = tid; i < 20 * 52; i += 256) {
            int jq = i / 52, kq = i % 52;
            W1s[i] = (kq < H) ? W1[jq * H + kq] : 0.f;
        }
        if (tid < 20) { b1s[tid] = b1[tid]; W2s[tid] = W2[tid]; }
        __syncthreads();
        const float bb2 = b2[0];

#pragma unroll
        for (int pass = 0; pass < 2; pass++) {
            const int q  = tid + pass * 256;          // 0..511 over both chunks
            const int c2 = blockIdx.x * 2 + (q >= B);
            const int qq = q & (B - 1);
            const int wu2 = c2 ? WU : 0;
            const float4* h4 = (const float4*)(g_buf0 + (size_t)c2 * SPANMAX * HP
                                               + (size_t)(wu2 + qq) * HP);
            float acc[20];
#pragma unroll
            for (int jq = 0; jq < 20; jq++) acc[jq] = b1s[jq];
#pragma unroll 4
            for (int kq = 0; kq < 13; kq++) {         // 52 cols; pads are 0
                float4 hv = h4[kq];
#pragma unroll
                for (int jq = 0; jq < 20; jq++) {
                    acc[jq] = fmaf(W1s[jq * 52 + 4 * kq + 0], hv.x, acc[jq]);
                    acc[jq] = fmaf(W1s[jq * 52 + 4 * kq + 1], hv.y, acc[jq]);
                    acc[jq] = fmaf(W1s[jq * 52 + 4 * kq + 2], hv.z, acc[jq]);
                    acc[jq] = fmaf(W1s[jq * 52 + 4 * kq + 3], hv.w, acc[jq]);
                }
            }
            float v = 0.f;
#pragma unroll
            for (int jq = 0; jq < 20; jq++) v = fmaf(W2s[jq], fmaxf(acc[jq], 0.f), v);
            out[c2 * B + qq] = 1.f / (1.f + expf(-(v + bb2)));
        }
    }
}

// ---------------------------------------------------------------------------
extern "C" void kernel_launch(void* const* d_in, const int* in_sizes, int n_in,
                              void* d_out, int out_size) {
    const float* x    = (const float*)d_in[0];
    const float* Wih0 = (const float*)d_in[1];
    const float* Wr   = (const float*)d_in[2];
    const float* Whh  = (const float*)d_in[3];
    const float* bih  = (const float*)d_in[4];
    const float* bhh  = (const float*)d_in[5];
    const float* W1   = (const float*)d_in[6];
    const float* b1   = (const float*)d_in[7];
    const float* W2   = (const float*)d_in[8];
    const float* b2   = (const float*)d_in[9];
    float* out = (float*)d_out;

    rnn_chunks<<<NC / 2, 256>>>(x, Wih0, Wr, Whh, bih, bhh, W1, b1, W2, b2, out);
}